// round 2
// baseline (speedup 1.0000x reference)
#include <cuda_runtime.h>
#include <math_constants.h>

// DotAttention: context[b,f] = softmax_t(<hd[b],he[b,t]>) . he[b,t,f]
// b=64, t=2048, f=1024, fp32.
// Flash-style online softmax, split-T partials + parallel combine.
// he (512MB) is streamed exactly once with evict-first hints.

#define BB 64
#define TT 2048
#define FF 1024
#define SPLITS 32
#define TCHUNK (TT / SPLITS)             // 64 rows per CTA
#define NWARPS 8
#define ROWS_PER_WARP (TCHUNK / NWARPS)  // 8

// scratch (allocation-free): partial unnormalized context + per-chunk (M, L)
__device__ float g_ctx[(size_t)BB * SPLITS * FF];   // 8 MB
__device__ float g_m[BB * SPLITS];
__device__ float g_l[BB * SPLITS];

__global__ __launch_bounds__(256)
void attn_partial_kernel(const float* __restrict__ hd,
                         const float* __restrict__ he) {
    const int s    = blockIdx.x;       // t-split
    const int b    = blockIdx.y;       // batch
    const int warp = threadIdx.x >> 5;
    const int lane = threadIdx.x & 31;

    // q: 32 floats per lane, lane-major so loads are coalesced. L2-resident.
    const float4* q4 = reinterpret_cast<const float4*>(hd + (size_t)b * FF);
    float4 q[8];
#pragma unroll
    for (int j = 0; j < 8; j++) q[j] = __ldg(&q4[j * 32 + lane]);

    float  m = -CUDART_INF_F;
    float  l = 0.0f;
    float4 acc[8];
#pragma unroll
    for (int j = 0; j < 8; j++) acc[j] = make_float4(0.f, 0.f, 0.f, 0.f);

    const int t_base = s * TCHUNK + warp;

#pragma unroll 2
    for (int r = 0; r < ROWS_PER_WARP; r++) {
        const int t = t_base + r * NWARPS;
        const float4* v4 = reinterpret_cast<const float4*>(
            he + ((size_t)b * TT + t) * FF);

        // evict-first: this stream is touched exactly once
        float4 v[8];
#pragma unroll
        for (int j = 0; j < 8; j++) v[j] = __ldcs(&v4[j * 32 + lane]);

        // dot(q, v) for this row
        float d = 0.0f;
#pragma unroll
        for (int j = 0; j < 8; j++) {
            d += v[j].x * q[j].x + v[j].y * q[j].y
               + v[j].z * q[j].z + v[j].w * q[j].w;
        }
#pragma unroll
        for (int off = 16; off; off >>= 1)
            d += __shfl_xor_sync(0xffffffffu, d, off);
        // d is warp-uniform -> uniform branch below (no divergence)

        if (d <= m) {
            const float p = __expf(d - m);
            l += p;
#pragma unroll
            for (int j = 0; j < 8; j++) {
                acc[j].x += p * v[j].x;
                acc[j].y += p * v[j].y;
                acc[j].z += p * v[j].z;
                acc[j].w += p * v[j].w;
            }
        } else {
            const float sc = __expf(m - d);   // 0 on first row (m = -inf)
            m = d;
            l = l * sc + 1.0f;                // p = exp(d - d) = 1
#pragma unroll
            for (int j = 0; j < 8; j++) {
                acc[j].x = acc[j].x * sc + v[j].x;
                acc[j].y = acc[j].y * sc + v[j].y;
                acc[j].z = acc[j].z * sc + v[j].z;
                acc[j].w = acc[j].w * sc + v[j].w;
            }
        }
    }

    // ---- combine the 8 warps of this CTA ----
    __shared__ float s_m[NWARPS];
    __shared__ float s_l[NWARPS];
    __shared__ float s_ctx[FF];

    for (int i = threadIdx.x; i < FF; i += 256) s_ctx[i] = 0.0f;
    if (lane == 0) { s_m[warp] = m; s_l[warp] = l; }
    __syncthreads();

    float M = s_m[0];
#pragma unroll
    for (int w = 1; w < NWARPS; w++) M = fmaxf(M, s_m[w]);

    const float sc = __expf(m - M);
#pragma unroll
    for (int j = 0; j < 8; j++) {
        const int f = (j * 32 + lane) * 4;
        atomicAdd(&s_ctx[f + 0], acc[j].x * sc);
        atomicAdd(&s_ctx[f + 1], acc[j].y * sc);
        atomicAdd(&s_ctx[f + 2], acc[j].z * sc);
        atomicAdd(&s_ctx[f + 3], acc[j].w * sc);
    }
    __syncthreads();

    const int chunk = b * SPLITS + s;
    if (threadIdx.x == 0) {
        float L = 0.0f;
#pragma unroll
        for (int w = 0; w < NWARPS; w++) L += s_l[w] * __expf(s_m[w] - M);
        g_m[chunk] = M;
        g_l[chunk] = L;
    }
    float* outp = g_ctx + (size_t)chunk * FF;
    for (int i = threadIdx.x; i < FF; i += 256) outp[i] = s_ctx[i];
}

// grid = (FF/128, BB), 128 threads: each thread owns one output element.
__global__ __launch_bounds__(128)
void attn_combine_kernel(float* __restrict__ out) {
    const int b = blockIdx.y;
    const int f = blockIdx.x * 128 + threadIdx.x;

    float M = -CUDART_INF_F;
#pragma unroll
    for (int s = 0; s < SPLITS; s++) M = fmaxf(M, g_m[b * SPLITS + s]);

    float L = 0.0f;
    float v = 0.0f;
#pragma unroll
    for (int s = 0; s < SPLITS; s++) {
        const float e = __expf(g_m[b * SPLITS + s] - M);
        L += g_l[b * SPLITS + s] * e;
        v += g_ctx[((size_t)b * SPLITS + s) * FF + f] * e;
    }
    out[(size_t)b * FF + f] = v / L;
}

extern "C" void kernel_launch(void* const* d_in, const int* in_sizes, int n_in,
                              void* d_out, int out_size) {
    const float* hd = (const float*)d_in[0];   // (64, 1024)
    const float* he = (const float*)d_in[1];   // (64, 2048, 1024)
    float* out = (float*)d_out;                // (64, 1024)
    (void)in_sizes; (void)n_in; (void)out_size;

    dim3 grid(SPLITS, BB);
    attn_partial_kernel<<<grid, 256>>>(hd, he);

    dim3 cgrid(FF / 128, BB);
    attn_combine_kernel<<<cgrid, 128>>>(out);
}

// round 3
// speedup vs baseline: 1.1551x; 1.1551x over previous
#include <cuda_runtime.h>
#include <math_constants.h>

// DotAttention: context[b,f] = softmax_t(<hd[b],he[b,t]>) . he[b,t,f]
// b=64, t=2048, f=1024, fp32.
// R3 = R1 partial (exact revert, 87.7us measured) + parallel combine.

#define BB 64
#define TT 2048
#define FF 1024
#define SPLITS 8
#define TCHUNK (TT / SPLITS)             // 256 rows per CTA
#define NWARPS 8
#define ROWS_PER_WARP (TCHUNK / NWARPS)  // 32

// scratch (allocation-free): partial unnormalized context + per-chunk (M, L)
__device__ float g_ctx[(size_t)BB * SPLITS * FF];   // 2 MB
__device__ float g_m[BB * SPLITS];
__device__ float g_l[BB * SPLITS];

__global__ __launch_bounds__(256)
void attn_partial_kernel(const float* __restrict__ hd,
                         const float* __restrict__ he) {
    const int s    = blockIdx.x;       // t-split
    const int b    = blockIdx.y;       // batch
    const int warp = threadIdx.x >> 5;
    const int lane = threadIdx.x & 31;

    // q: 32 floats per lane, lane-major so loads are coalesced.
    const float4* q4 = reinterpret_cast<const float4*>(hd + (size_t)b * FF);
    float4 q[8];
#pragma unroll
    for (int j = 0; j < 8; j++) q[j] = q4[j * 32 + lane];

    float  m = -CUDART_INF_F;
    float  l = 0.0f;
    float4 acc[8];
#pragma unroll
    for (int j = 0; j < 8; j++) acc[j] = make_float4(0.f, 0.f, 0.f, 0.f);

    const int t_base = s * TCHUNK + warp;

    for (int r = 0; r < ROWS_PER_WARP; r++) {
        const int t = t_base + r * NWARPS;
        const float4* v4 = reinterpret_cast<const float4*>(
            he + ((size_t)b * TT + t) * FF);

        float4 v[8];
#pragma unroll
        for (int j = 0; j < 8; j++) v[j] = v4[j * 32 + lane];

        // dot(q, v) for this row
        float d = 0.0f;
#pragma unroll
        for (int j = 0; j < 8; j++) {
            d += v[j].x * q[j].x + v[j].y * q[j].y
               + v[j].z * q[j].z + v[j].w * q[j].w;
        }
#pragma unroll
        for (int off = 16; off; off >>= 1)
            d += __shfl_xor_sync(0xffffffffu, d, off);
        // d is warp-uniform now -> uniform branch below (no divergence)

        if (d <= m) {
            const float p = __expf(d - m);
            l += p;
#pragma unroll
            for (int j = 0; j < 8; j++) {
                acc[j].x += p * v[j].x;
                acc[j].y += p * v[j].y;
                acc[j].z += p * v[j].z;
                acc[j].w += p * v[j].w;
            }
        } else {
            const float sc = __expf(m - d);   // 0 on first row (m = -inf)
            m = d;
            l = l * sc + 1.0f;                // p = exp(d - d) = 1
#pragma unroll
            for (int j = 0; j < 8; j++) {
                acc[j].x = acc[j].x * sc + v[j].x;
                acc[j].y = acc[j].y * sc + v[j].y;
                acc[j].z = acc[j].z * sc + v[j].z;
                acc[j].w = acc[j].w * sc + v[j].w;
            }
        }
    }

    // ---- combine the 8 warps of this CTA ----
    __shared__ float s_m[NWARPS];
    __shared__ float s_l[NWARPS];
    __shared__ float s_ctx[FF];

    for (int i = threadIdx.x; i < FF; i += 256) s_ctx[i] = 0.0f;
    if (lane == 0) { s_m[warp] = m; s_l[warp] = l; }
    __syncthreads();

    float M = s_m[0];
#pragma unroll
    for (int w = 1; w < NWARPS; w++) M = fmaxf(M, s_m[w]);

    const float sc = __expf(m - M);
#pragma unroll
    for (int j = 0; j < 8; j++) {
        const int f = (j * 32 + lane) * 4;
        atomicAdd(&s_ctx[f + 0], acc[j].x * sc);
        atomicAdd(&s_ctx[f + 1], acc[j].y * sc);
        atomicAdd(&s_ctx[f + 2], acc[j].z * sc);
        atomicAdd(&s_ctx[f + 3], acc[j].w * sc);
    }
    __syncthreads();

    const int chunk = b * SPLITS + s;
    if (threadIdx.x == 0) {
        float L = 0.0f;
#pragma unroll
        for (int w = 0; w < NWARPS; w++) L += s_l[w] * __expf(s_m[w] - M);
        g_m[chunk] = M;
        g_l[chunk] = L;
    }
    float* outp = g_ctx + (size_t)chunk * FF;
    for (int i = threadIdx.x; i < FF; i += 256) outp[i] = s_ctx[i];
}

// grid = (FF/128, BB), 128 threads: each thread owns one output element.
// g_ctx is only 2MB and freshly written -> L2-resident reads.
__global__ __launch_bounds__(128)
void attn_combine_kernel(float* __restrict__ out) {
    const int b = blockIdx.y;
    const int f = blockIdx.x * 128 + threadIdx.x;

    float M = -CUDART_INF_F;
#pragma unroll
    for (int s = 0; s < SPLITS; s++) M = fmaxf(M, g_m[b * SPLITS + s]);

    float L = 0.0f;
    float v = 0.0f;
#pragma unroll
    for (int s = 0; s < SPLITS; s++) {
        const float e = __expf(g_m[b * SPLITS + s] - M);
        L += g_l[b * SPLITS + s] * e;
        v += g_ctx[((size_t)b * SPLITS + s) * FF + f] * e;
    }
    out[(size_t)b * FF + f] = v / L;
}

extern "C" void kernel_launch(void* const* d_in, const int* in_sizes, int n_in,
                              void* d_out, int out_size) {
    const float* hd = (const float*)d_in[0];   // (64, 1024)
    const float* he = (const float*)d_in[1];   // (64, 2048, 1024)
    float* out = (float*)d_out;                // (64, 1024)
    (void)in_sizes; (void)n_in; (void)out_size;

    dim3 grid(SPLITS, BB);
    attn_partial_kernel<<<grid, 256>>>(hd, he);

    dim3 cgrid(FF / 128, BB);
    attn_combine_kernel<<<cgrid, 128>>>(out);
}